// round 3
// baseline (speedup 1.0000x reference)
#include <cuda_runtime.h>
#include <math.h>

// ---------------------------------------------------------------------------
// CrystalGraphAttention  (B=8, N=1024, D=256, H=8, dk=dv=64)
//
//   q,k,v = X @ W{q,k,v}         -> [B,H,N,64]   (kernel 1)
//   kT    = transpose(k)         -> [B,H,64,N]   (kernel 1b)
//   S = (qk/8 + (1-mask)*NEG)*dw ; softmax ; O = P@V  (kernel 2, flash-style)
//   out = ctx @ Wo + bo          -> [B,N,256]    (kernel 3)
// ---------------------------------------------------------------------------

#define NEGBIG (-1.0e9f)

// scratch (device globals; allocation-free per harness rules)
static __device__ float g_q [8 * 8 * 1024 * 64];    // [B,H,N,64] 16MB
static __device__ float g_k [8 * 8 * 1024 * 64];
static __device__ float g_v [8 * 8 * 1024 * 64];
static __device__ float g_kT[8 * 8 * 64 * 1024];    // [B,H,64,N] 16MB
static __device__ float g_ctx[8 * 1024 * 512];      // [B*N, H*64] 16MB

// ---------------------------------------------------------------------------
// Kernel 1: fused QKV projection.
// grid = (64 Mtiles, 8 heads, 3 weights), block = 256.
// Tile: 128(M) x 64(N), K-steps of 32.  Thread: 8x4 accumulators.
// ---------------------------------------------------------------------------
__global__ __launch_bounds__(256) void qkv_kernel(
    const float* __restrict__ X,
    const float* __restrict__ Wq,
    const float* __restrict__ Wk,
    const float* __restrict__ Wv)
{
    __shared__ float As[128 * 33];
    __shared__ float Bs[32 * 68];

    const int tid = threadIdx.x;
    const int mt = blockIdx.x;            // 0..63
    const int h  = blockIdx.y;            // 0..7
    const int w  = blockIdx.z;            // 0..2
    const float* W = (w == 0) ? Wq : (w == 1) ? Wk : Wv;
    float* Out     = (w == 0) ? g_q : (w == 1) ? g_k : g_v;

    const int tm = tid >> 4;              // 0..15 (row group of 8)
    const int tn = tid & 15;              // 0..15 (col group of 4)
    const int lr = tid >> 3;              // 0..31 A-load row base
    const int lc = tid & 7;               // 0..7  A-load col group
    const int br = tid >> 4;              // 0..15 B-load row base
    const int bc = tid & 15;              // 0..15 B-load col group

    float acc[8][4];
    #pragma unroll
    for (int i = 0; i < 8; i++)
        #pragma unroll
        for (int j = 0; j < 4; j++) acc[i][j] = 0.f;

    for (int k0 = 0; k0 < 256; k0 += 32) {
        #pragma unroll
        for (int t = 0; t < 4; t++) {
            int m = lr + 32 * t;
            float4 xv = *(const float4*)&X[(size_t)(mt * 128 + m) * 256 + k0 + lc * 4];
            As[m * 33 + lc * 4 + 0] = xv.x;
            As[m * 33 + lc * 4 + 1] = xv.y;
            As[m * 33 + lc * 4 + 2] = xv.z;
            As[m * 33 + lc * 4 + 3] = xv.w;
        }
        #pragma unroll
        for (int t = 0; t < 2; t++) {
            int k = br + 16 * t;
            float4 wv = *(const float4*)&W[(size_t)(k0 + k) * 512 + h * 64 + bc * 4];
            *(float4*)&Bs[k * 68 + bc * 4] = wv;
        }
        __syncthreads();

        #pragma unroll 8
        for (int kk = 0; kk < 32; kk++) {
            float a[8];
            #pragma unroll
            for (int i = 0; i < 8; i++) a[i] = As[(tm * 8 + i) * 33 + kk];
            float4 bv = *(const float4*)&Bs[kk * 68 + tn * 4];
            #pragma unroll
            for (int i = 0; i < 8; i++) {
                acc[i][0] += a[i] * bv.x;
                acc[i][1] += a[i] * bv.y;
                acc[i][2] += a[i] * bv.z;
                acc[i][3] += a[i] * bv.w;
            }
        }
        __syncthreads();
    }

    #pragma unroll
    for (int i = 0; i < 8; i++) {
        int m = mt * 128 + tm * 8 + i;
        int b = m >> 10, s = m & 1023;
        float4 r;
        r.x = acc[i][0]; r.y = acc[i][1]; r.z = acc[i][2]; r.w = acc[i][3];
        *(float4*)&Out[(size_t)((b * 8 + h) * 1024 + s) * 64 + tn * 4] = r;
    }
}

// ---------------------------------------------------------------------------
// Kernel 1b: K transpose  [BH,1024,64] -> [BH,64,1024]
// grid = (32, 2, 64), block = (32, 8)
// ---------------------------------------------------------------------------
__global__ __launch_bounds__(256) void ktrans_kernel()
{
    __shared__ float tile[32][33];
    const int bh = blockIdx.z;
    const int t0 = blockIdx.x * 32;
    const int d0 = blockIdx.y * 32;
    const int tx = threadIdx.x, ty = threadIdx.y;

    #pragma unroll
    for (int i = ty; i < 32; i += 8)
        tile[i][tx] = g_k[(size_t)(bh * 1024 + t0 + i) * 64 + d0 + tx];
    __syncthreads();
    #pragma unroll
    for (int i = ty; i < 32; i += 8)
        g_kT[(size_t)(bh * 64 + d0 + i) * 1024 + t0 + tx] = tile[tx][i];
}

// ---------------------------------------------------------------------------
// Kernel 2: flash-style attention.
// grid = (16 qtiles, 8 heads, 8 batches), block = 256.
// Per block: Q tile 64x64 resident; loop 16 key tiles of 64.
// Thread (ty,tx) owns rows ty*4..+3, cols tx*4..+3 of each 64x64 tile.
// K tile loaded from g_kT in [d][t] layout -> conflict-free MMA reads.
// P tile aliases K tile smem -> exactly 48KB static shared.
// ---------------------------------------------------------------------------
__global__ __launch_bounds__(256) void attn_kernel(
    const float* __restrict__ em,     // [B,1,N,N]
    const float* __restrict__ dw)     // [B,N]
{
    __shared__ float Qs [64 * 64];
    __shared__ float KPs[64 * 64];    // Kt tile [d][t], later reused as P tile
    __shared__ float Vs [64 * 64];    // V tile  [t][d]

    const int tid = threadIdx.x;
    const int qt = blockIdx.x, h = blockIdx.y, b = blockIdx.z;
    const int ty = tid >> 4, tx = tid & 15;
    const int lr = tid >> 4, lc = tid & 15;

    const float* qbase  = &g_q [(size_t)((b * 8 + h) * 1024 + qt * 64) * 64];
    const float* ktbase = &g_kT[(size_t)(b * 8 + h) * 64 * 1024];
    const float* vbase  = &g_v [(size_t)(b * 8 + h) * 1024 * 64];

    #pragma unroll
    for (int t = 0; t < 4; t++) {
        int r = lr + 16 * t;
        *(float4*)&Qs[r * 64 + lc * 4] = *(const float4*)&qbase[r * 64 + lc * 4];
    }

    float o[4][4], mi[4], li[4];
    #pragma unroll
    for (int i = 0; i < 4; i++) {
        mi[i] = -1e30f; li[i] = 0.f;
        #pragma unroll
        for (int j = 0; j < 4; j++) o[i][j] = 0.f;
    }

    for (int kt = 0; kt < 16; kt++) {
        __syncthreads();   // previous tile's P/V reads done before overwrite
        #pragma unroll
        for (int t = 0; t < 4; t++) {
            int r = lr + 16 * t;
            // KPs[d][t] = kT[d][kt*64 + t]
            *(float4*)&KPs[r * 64 + lc * 4] =
                *(const float4*)&ktbase[(size_t)r * 1024 + kt * 64 + lc * 4];
            // Vs[t][d]
            *(float4*)&Vs[r * 64 + lc * 4] =
                *(const float4*)&vbase[(size_t)(kt * 64 + r) * 64 + lc * 4];
        }
        __syncthreads();

        // --- S = Q K^T (64x64x64):  acc[i][j] = sum_d Q[s][d] * Kt[d][t] ---
        float acc[4][4];
        #pragma unroll
        for (int i = 0; i < 4; i++)
            #pragma unroll
            for (int j = 0; j < 4; j++) acc[i][j] = 0.f;

        #pragma unroll 8
        for (int kk = 0; kk < 64; kk++) {
            float a[4];
            #pragma unroll
            for (int i = 0; i < 4; i++) a[i] = Qs[(ty * 4 + i) * 64 + kk];
            float4 bv = *(const float4*)&KPs[kk * 64 + tx * 4];
            #pragma unroll
            for (int i = 0; i < 4; i++) {
                acc[i][0] += a[i] * bv.x;
                acc[i][1] += a[i] * bv.y;
                acc[i][2] += a[i] * bv.z;
                acc[i][3] += a[i] * bv.w;
            }
        }
        __syncthreads();   // K reads done; KPs will become P

        // --- mask + distance modulation + online softmax ---
        float4 dv = *(const float4*)&dw[b * 1024 + kt * 64 + tx * 4];
        float p[4][4];
        #pragma unroll
        for (int i = 0; i < 4; i++) {
            int qg = qt * 64 + ty * 4 + i;
            float4 mv = *(const float4*)&em[(size_t)b * 1024 * 1024 +
                                            (size_t)qg * 1024 + kt * 64 + tx * 4];
            float s0 = (acc[i][0] * 0.125f + (1.f - mv.x) * NEGBIG) * dv.x;
            float s1 = (acc[i][1] * 0.125f + (1.f - mv.y) * NEGBIG) * dv.y;
            float s2 = (acc[i][2] * 0.125f + (1.f - mv.z) * NEGBIG) * dv.z;
            float s3 = (acc[i][3] * 0.125f + (1.f - mv.w) * NEGBIG) * dv.w;

            float rm = fmaxf(fmaxf(s0, s1), fmaxf(s2, s3));
            #pragma unroll
            for (int off = 8; off > 0; off >>= 1)
                rm = fmaxf(rm, __shfl_xor_sync(0xffffffffu, rm, off));

            float nm   = fmaxf(mi[i], rm);
            float corr = __expf(mi[i] - nm);
            float p0 = __expf(s0 - nm);
            float p1 = __expf(s1 - nm);
            float p2 = __expf(s2 - nm);
            float p3 = __expf(s3 - nm);
            float rs = (p0 + p1) + (p2 + p3);
            #pragma unroll
            for (int off = 8; off > 0; off >>= 1)
                rs += __shfl_xor_sync(0xffffffffu, rs, off);

            li[i] = li[i] * corr + rs;
            mi[i] = nm;
            o[i][0] *= corr; o[i][1] *= corr; o[i][2] *= corr; o[i][3] *= corr;
            p[i][0] = p0; p[i][1] = p1; p[i][2] = p2; p[i][3] = p3;
        }

        #pragma unroll
        for (int i = 0; i < 4; i++) {
            float4 pv; pv.x = p[i][0]; pv.y = p[i][1]; pv.z = p[i][2]; pv.w = p[i][3];
            *(float4*)&KPs[(ty * 4 + i) * 64 + tx * 4] = pv;
        }
        __syncthreads();

        // --- O += P V (64x64x64) ---
        #pragma unroll 8
        for (int t = 0; t < 64; t++) {
            float pr[4];
            #pragma unroll
            for (int i = 0; i < 4; i++) pr[i] = KPs[(ty * 4 + i) * 64 + t];
            float4 vv = *(const float4*)&Vs[t * 64 + tx * 4];
            #pragma unroll
            for (int i = 0; i < 4; i++) {
                o[i][0] += pr[i] * vv.x;
                o[i][1] += pr[i] * vv.y;
                o[i][2] += pr[i] * vv.z;
                o[i][3] += pr[i] * vv.w;
            }
        }
    }

    #pragma unroll
    for (int i = 0; i < 4; i++) {
        int qg = qt * 64 + ty * 4 + i;
        float inv = 1.f / li[i];
        float4 r;
        r.x = o[i][0] * inv; r.y = o[i][1] * inv;
        r.z = o[i][2] * inv; r.w = o[i][3] * inv;
        *(float4*)&g_ctx[(size_t)(b * 1024 + qg) * 512 + h * 64 + tx * 4] = r;
    }
}

// ---------------------------------------------------------------------------
// Kernel 3: output projection  out = ctx @ Wo + bo.
// grid = (64 Mtiles, 4 Ntiles), block = 256.  Same 128x64 tiling, K=512.
// ---------------------------------------------------------------------------
__global__ __launch_bounds__(256) void oproj_kernel(
    const float* __restrict__ Wo,
    const float* __restrict__ bo,
    float* __restrict__ out)
{
    __shared__ float As[128 * 33];
    __shared__ float Bs[32 * 68];

    const int tid = threadIdx.x;
    const int mt = blockIdx.x;        // 0..63
    const int nt = blockIdx.y;        // 0..3

    const int tm = tid >> 4, tn = tid & 15;
    const int lr = tid >> 3, lc = tid & 7;
    const int br = tid >> 4, bc = tid & 15;

    float acc[8][4];
    #pragma unroll
    for (int i = 0; i < 8; i++)
        #pragma unroll
        for (int j = 0; j < 4; j++) acc[i][j] = 0.f;

    for (int k0 = 0; k0 < 512; k0 += 32) {
        #pragma unroll
        for (int t = 0; t < 4; t++) {
            int m = lr + 32 * t;
            float4 xv = *(const float4*)&g_ctx[(size_t)(mt * 128 + m) * 512 + k0 + lc * 4];
            As[m * 33 + lc * 4 + 0] = xv.x;
            As[m * 33 + lc * 4 + 1] = xv.y;
            As[m * 33 + lc * 4 + 2] = xv.z;
            As[m * 33 + lc * 4 + 3] = xv.w;
        }
        #pragma unroll
        for (int t = 0; t < 2; t++) {
            int k = br + 16 * t;
            float4 wv = *(const float4*)&Wo[(size_t)(k0 + k) * 256 + nt * 64 + bc * 4];
            *(float4*)&Bs[k * 68 + bc * 4] = wv;
        }
        __syncthreads();

        #pragma unroll 8
        for (int kk = 0; kk < 32; kk++) {
            float a[8];
            #pragma unroll
            for (int i = 0; i < 8; i++) a[i] = As[(tm * 8 + i) * 33 + kk];
            float4 bv = *(const float4*)&Bs[kk * 68 + tn * 4];
            #pragma unroll
            for (int i = 0; i < 8; i++) {
                acc[i][0] += a[i] * bv.x;
                acc[i][1] += a[i] * bv.y;
                acc[i][2] += a[i] * bv.z;
                acc[i][3] += a[i] * bv.w;
            }
        }
        __syncthreads();
    }

    float4 bv = *(const float4*)&bo[nt * 64 + tn * 4];
    #pragma unroll
    for (int i = 0; i < 8; i++) {
        int m = mt * 128 + tm * 8 + i;
        float4 r;
        r.x = acc[i][0] + bv.x; r.y = acc[i][1] + bv.y;
        r.z = acc[i][2] + bv.z; r.w = acc[i][3] + bv.w;
        *(float4*)&out[(size_t)m * 256 + nt * 64 + tn * 4] = r;
    }
}

// ---------------------------------------------------------------------------
extern "C" void kernel_launch(void* const* d_in, const int* in_sizes, int n_in,
                              void* d_out, int out_size)
{
    const float* X  = (const float*)d_in[0];   // node_features [8,1024,256]
    const float* em = (const float*)d_in[1];   // edge_mask     [8,1,1024,1024]
    const float* dw = (const float*)d_in[2];   // distance_weights [8,1024]
    const float* Wq = (const float*)d_in[3];
    const float* Wk = (const float*)d_in[4];
    const float* Wv = (const float*)d_in[5];
    const float* Wo = (const float*)d_in[6];
    const float* bo = (const float*)d_in[7];
    float* out = (float*)d_out;

    qkv_kernel  <<<dim3(64, 8, 3), 256>>>(X, Wq, Wk, Wv);
    ktrans_kernel<<<dim3(32, 2, 64), dim3(32, 8)>>>();
    attn_kernel <<<dim3(16, 8, 8), 256>>>(em, dw);
    oproj_kernel<<<dim3(64, 4, 1), 256>>>(Wo, bo, out);
}